// round 3
// baseline (speedup 1.0000x reference)
#include <cuda_runtime.h>
#include <cstdint>

#define NND 50000
#define FIN 128
#define FHID 128
#define FOUT 64

// ---------------- scratch (static device allocations; no cudaMalloc) ----------------
__device__ __align__(256) float g_xw1 [NND * FHID];   // x @ Wc1
__device__ __align__(256) float g_agg1[NND * FHID];   // layer-1 neighbor aggregate
__device__ __align__(256) float g_xw2 [NND * FOUT];   // h @ Wc2
__device__ __align__(256) float g_agg2[NND * FOUT];   // layer-2 neighbor aggregate
__device__ __align__(256) float g_AB  [NND * 2 * FOUT]; // per-node [A|B] = z @ [W1_top | W1_bot]
__device__ __align__(256) float g_dinv[NND];
__device__ __align__(256) int   g_deg [NND];
__device__ int g_f64[2];   // [0]: edge_index is int64, [1]: edge_label_index is int64

// ---------------- helpers ----------------
__device__ __forceinline__ int ld_idx(const void* p, long long pos, int is64) {
    return is64 ? (int)((const long long*)p)[pos] : ((const int*)p)[pos];
}

__device__ __forceinline__ void red_add_v4(float* ptr, float4 v) {
    asm volatile("red.global.add.v4.f32 [%0], {%1,%2,%3,%4};"
                 :: "l"(ptr), "f"(v.x), "f"(v.y), "f"(v.z), "f"(v.w)
                 : "memory");
}

// ---------------- kernels ----------------
__global__ void zero_kernel(int M) {
    long long stride = (long long)gridDim.x * blockDim.x;
    long long g = (long long)blockIdx.x * blockDim.x + threadIdx.x;
    float4 z4 = make_float4(0.f, 0.f, 0.f, 0.f);
    long long n1 = (long long)M * (FHID / 4);
    for (long long i = g; i < n1; i += stride) ((float4*)g_agg1)[i] = z4;
    long long n2 = (long long)M * (FOUT / 4);
    for (long long i = g; i < n2; i += stride) ((float4*)g_agg2)[i] = z4;
    for (long long i = g; i < M; i += stride) g_deg[i] = 0;
}

__global__ void detect_kernel(const void* ei, const void* eli, int n_nodes) {
    if (blockIdx.x == 0 && threadIdx.x == 0) {
        const long long* a = (const long long*)ei;
        int ok = 1;
        for (int k = 0; k < 64; k++) { long long v = a[k]; if (v < 0 || v >= n_nodes) { ok = 0; break; } }
        g_f64[0] = ok;
        const long long* b = (const long long*)eli;
        ok = 1;
        for (int k = 0; k < 64; k++) { long long v = b[k]; if (v < 0 || v >= n_nodes) { ok = 0; break; } }
        g_f64[1] = ok;
    }
}

__global__ void deg_kernel(const void* ei, long long E) {
    long long e = (long long)blockIdx.x * blockDim.x + threadIdx.x;
    if (e >= E) return;
    int f = g_f64[0];
    int d = ld_idx(ei, E + e, f);
    atomicAdd(&g_deg[d], 1);
}

__global__ void dinv_kernel(int M) {
    int i = blockIdx.x * blockDim.x + threadIdx.x;
    if (i >= M) return;
    g_dinv[i] = rsqrtf((float)g_deg[i] + 1.0f);
}

// xw1 = x @ Wc1  ([M,128] @ [128,128])
__global__ void gemm1_kernel(const float* __restrict__ X, const float* __restrict__ W, int M) {
    extern __shared__ float sm[];
    float* Ws = sm;              // 128*128
    float* Xs = sm + 128 * 128;  // 64*128
    for (int i = threadIdx.x; i < 128 * 128 / 4; i += blockDim.x)
        ((float4*)Ws)[i] = ((const float4*)W)[i];
    int row0 = blockIdx.x * 64;
    int rows = min(64, M - row0);
    for (int i = threadIdx.x; i < rows * 32; i += blockDim.x)
        ((float4*)Xs)[i] = ((const float4*)X)[(long long)row0 * 32 + i];
    __syncthreads();

    int rowg = threadIdx.x >> 4;   // 0..15 -> 4 rows each
    int colg = threadIdx.x & 15;   // 0..15 -> 8 cols each
    float acc[4][8];
#pragma unroll
    for (int r = 0; r < 4; r++)
#pragma unroll
        for (int c = 0; c < 8; c++) acc[r][c] = 0.f;

    const float* xb = Xs + rowg * 4 * 128;
    const float* wb = Ws + colg * 8;
#pragma unroll 4
    for (int k = 0; k < 128; k++) {
        float xr[4];
#pragma unroll
        for (int r = 0; r < 4; r++) xr[r] = xb[r * 128 + k];
        float w[8];
        *(float4*)&w[0] = *(const float4*)(wb + k * 128);
        *(float4*)&w[4] = *(const float4*)(wb + k * 128 + 4);
#pragma unroll
        for (int r = 0; r < 4; r++)
#pragma unroll
            for (int c = 0; c < 8; c++) acc[r][c] = fmaf(xr[r], w[c], acc[r][c]);
    }
#pragma unroll
    for (int r = 0; r < 4; r++) {
        int row = row0 + rowg * 4 + r;
        if (row < M) {
            float4* o = (float4*)(g_xw1 + (long long)row * 128 + colg * 8);
            o[0] = make_float4(acc[r][0], acc[r][1], acc[r][2], acc[r][3]);
            o[1] = make_float4(acc[r][4], acc[r][5], acc[r][6], acc[r][7]);
        }
    }
}

// layer-1 scatter: agg1[dst] += xw1[src] * dinv[src]*dinv[dst]   (warp per edge, float4 lanes)
__global__ void scatter1_kernel(const void* ei, long long E) {
    long long g = (long long)blockIdx.x * blockDim.x + threadIdx.x;
    long long w = g >> 5;
    if (w >= E) return;
    int lane = threadIdx.x & 31;
    int f = g_f64[0];
    int s = ld_idx(ei, w, f);
    int d = ld_idx(ei, E + w, f);
    float nrm = g_dinv[s] * g_dinv[d];
    float4 v = ((const float4*)(g_xw1 + (long long)s * FHID))[lane];
    v.x *= nrm; v.y *= nrm; v.z *= nrm; v.w *= nrm;
    red_add_v4(g_agg1 + (long long)d * FHID + lane * 4, v);
}

// h = relu(agg1 + xw1*dinv^2 + bc1) computed in smem; xw2 = h @ Wc2  ([M,128]@[128,64])
__global__ void gemm2_kernel(const float* __restrict__ Wc2, const float* __restrict__ bc1, int M) {
    extern __shared__ float sm[];
    float* Ws  = sm;                 // 128*64
    float* Hs  = Ws + 128 * 64;      // 64*128
    float* b1s = Hs + 64 * 128;      // 128
    float* dvs = b1s + 128;          // 64
    for (int i = threadIdx.x; i < 128 * 64 / 4; i += blockDim.x)
        ((float4*)Ws)[i] = ((const float4*)Wc2)[i];
    if (threadIdx.x < 128) b1s[threadIdx.x] = bc1[threadIdx.x];
    int row0 = blockIdx.x * 64;
    int rows = min(64, M - row0);
    if (threadIdx.x < rows) dvs[threadIdx.x] = g_dinv[row0 + threadIdx.x];
    __syncthreads();

    for (int i = threadIdx.x; i < rows * 32; i += blockDim.x) {
        int r = i >> 5, c = i & 31;
        float dv = dvs[r]; float dv2 = dv * dv;
        float4 a = ((const float4*)g_agg1)[(long long)(row0 + r) * 32 + c];
        float4 x = ((const float4*)g_xw1)[(long long)(row0 + r) * 32 + c];
        float4 h;
        h.x = fmaxf(fmaf(x.x, dv2, a.x) + b1s[c * 4 + 0], 0.f);
        h.y = fmaxf(fmaf(x.y, dv2, a.y) + b1s[c * 4 + 1], 0.f);
        h.z = fmaxf(fmaf(x.z, dv2, a.z) + b1s[c * 4 + 2], 0.f);
        h.w = fmaxf(fmaf(x.w, dv2, a.w) + b1s[c * 4 + 3], 0.f);
        ((float4*)Hs)[i] = h;
    }
    __syncthreads();

    int rowg = threadIdx.x >> 4;   // 4 rows each
    int colg = threadIdx.x & 15;   // 4 cols each
    float acc[4][4];
#pragma unroll
    for (int r = 0; r < 4; r++)
#pragma unroll
        for (int c = 0; c < 4; c++) acc[r][c] = 0.f;
    const float* xb = Hs + rowg * 4 * 128;
    const float* wb = Ws + colg * 4;
#pragma unroll 4
    for (int k = 0; k < 128; k++) {
        float xr[4];
#pragma unroll
        for (int r = 0; r < 4; r++) xr[r] = xb[r * 128 + k];
        float4 w = *(const float4*)(wb + k * 64);
#pragma unroll
        for (int r = 0; r < 4; r++) {
            acc[r][0] = fmaf(xr[r], w.x, acc[r][0]);
            acc[r][1] = fmaf(xr[r], w.y, acc[r][1]);
            acc[r][2] = fmaf(xr[r], w.z, acc[r][2]);
            acc[r][3] = fmaf(xr[r], w.w, acc[r][3]);
        }
    }
#pragma unroll
    for (int r = 0; r < 4; r++) {
        int row = row0 + rowg * 4 + r;
        if (row < M)
            *(float4*)(g_xw2 + (long long)row * 64 + colg * 4) =
                make_float4(acc[r][0], acc[r][1], acc[r][2], acc[r][3]);
    }
}

// layer-2 scatter: warp handles 2 edges, 16 lanes x float4 each
__global__ void scatter2_kernel(const void* ei, long long E) {
    long long g = (long long)blockIdx.x * blockDim.x + threadIdx.x;
    long long w = g >> 5;
    int lane = threadIdx.x & 31;
    long long e = w * 2 + (lane >> 4);
    if (e >= E) return;
    int l = lane & 15;
    int f = g_f64[0];
    int s = ld_idx(ei, e, f);
    int d = ld_idx(ei, E + e, f);
    float nrm = g_dinv[s] * g_dinv[d];
    float4 v = ((const float4*)(g_xw2 + (long long)s * FOUT))[l];
    v.x *= nrm; v.y *= nrm; v.z *= nrm; v.w *= nrm;
    red_add_v4(g_agg2 + (long long)d * FOUT + l * 4, v);
}

// z = agg2 + xw2*dinv^2 + bc2 (smem); AB = z @ W1r  ([M,64]@[64,128]) where
// W1r[k][c] = W1[k][c] (c<64) else W1[64+k][c-64]
__global__ void gemm3_kernel(const float* __restrict__ W1, const float* __restrict__ bc2, int M) {
    extern __shared__ float sm[];
    float* Ws  = sm;               // 64*128 (rearranged W1)
    float* Zs  = Ws + 64 * 128;    // 64*64
    float* b2s = Zs + 64 * 64;     // 64
    float* dvs = b2s + 64;         // 64
    for (int i = threadIdx.x; i < 64 * 128; i += blockDim.x) {
        int k = i >> 7, c = i & 127;
        Ws[i] = (c < 64) ? W1[k * 64 + c] : W1[(64 + k) * 64 + (c - 64)];
    }
    if (threadIdx.x < 64) b2s[threadIdx.x] = bc2[threadIdx.x];
    int row0 = blockIdx.x * 64;
    int rows = min(64, M - row0);
    if (threadIdx.x < rows) dvs[threadIdx.x] = g_dinv[row0 + threadIdx.x];
    __syncthreads();

    for (int i = threadIdx.x; i < rows * 16; i += blockDim.x) {
        int r = i >> 4, c = i & 15;
        float dv = dvs[r]; float dv2 = dv * dv;
        float4 a = ((const float4*)g_agg2)[(long long)(row0 + r) * 16 + c];
        float4 x = ((const float4*)g_xw2)[(long long)(row0 + r) * 16 + c];
        float4 z;
        z.x = fmaf(x.x, dv2, a.x) + b2s[c * 4 + 0];
        z.y = fmaf(x.y, dv2, a.y) + b2s[c * 4 + 1];
        z.z = fmaf(x.z, dv2, a.z) + b2s[c * 4 + 2];
        z.w = fmaf(x.w, dv2, a.w) + b2s[c * 4 + 3];
        ((float4*)Zs)[i] = z;
    }
    __syncthreads();

    int rowg = threadIdx.x >> 4;   // 4 rows
    int colg = threadIdx.x & 15;   // 8 cols
    float acc[4][8];
#pragma unroll
    for (int r = 0; r < 4; r++)
#pragma unroll
        for (int c = 0; c < 8; c++) acc[r][c] = 0.f;
    const float* xb = Zs + rowg * 4 * 64;
    const float* wb = Ws + colg * 8;
#pragma unroll 4
    for (int k = 0; k < 64; k++) {
        float xr[4];
#pragma unroll
        for (int r = 0; r < 4; r++) xr[r] = xb[r * 64 + k];
        float w[8];
        *(float4*)&w[0] = *(const float4*)(wb + k * 128);
        *(float4*)&w[4] = *(const float4*)(wb + k * 128 + 4);
#pragma unroll
        for (int r = 0; r < 4; r++)
#pragma unroll
            for (int c = 0; c < 8; c++) acc[r][c] = fmaf(xr[r], w[c], acc[r][c]);
    }
#pragma unroll
    for (int r = 0; r < 4; r++) {
        int row = row0 + rowg * 4 + r;
        if (row < M) {
            float4* o = (float4*)(g_AB + (long long)row * 128 + colg * 8);
            o[0] = make_float4(acc[r][0], acc[r][1], acc[r][2], acc[r][3]);
            o[1] = make_float4(acc[r][4], acc[r][5], acc[r][6], acc[r][7]);
        }
    }
}

// decode: warp per label edge
__global__ void decode_kernel(const void* eli, const float* __restrict__ b1,
                              const float* __restrict__ W2, const float* __restrict__ b2,
                              float* __restrict__ out, long long EL) {
    long long g = (long long)blockIdx.x * blockDim.x + threadIdx.x;
    long long e = g >> 5;
    if (e >= EL) return;
    int lane = threadIdx.x & 31;
    int f = g_f64[1];
    int i = ld_idx(eli, e, f);
    int j = ld_idx(eli, EL + e, f);
    const float* zi = g_AB + (long long)i * 128;
    const float* zj = g_AB + (long long)j * 128;
    int c0 = lane, c1 = lane + 32;
    float b1a = __ldg(b1 + c0), b1b = __ldg(b1 + c1);
    float w2a = __ldg(W2 + c0), w2b = __ldg(W2 + c1);
    float Aia = zi[c0], Aib = zi[c1], Bia = zi[64 + c0], Bib = zi[64 + c1];
    float Aja = zj[c0], Ajb = zj[c1], Bja = zj[64 + c0], Bjb = zj[64 + c1];
    float s = fmaxf(Aia + Bja + b1a, 0.f) * w2a + fmaxf(Aib + Bjb + b1b, 0.f) * w2b
            + fmaxf(Aja + Bia + b1a, 0.f) * w2a + fmaxf(Ajb + Bib + b1b, 0.f) * w2b;
#pragma unroll
    for (int o = 16; o; o >>= 1) s += __shfl_xor_sync(0xffffffffu, s, o);
    if (lane == 0) {
        float o1 = 0.5f * s + __ldg(b2);
        out[e]      = -o1;
        out[EL + e] =  o1;
    }
}

// ---------------- launch ----------------
extern "C" void kernel_launch(void* const* d_in, const int* in_sizes, int n_in,
                              void* d_out, int out_size) {
    const float* x   = (const float*)d_in[0];
    const void*  ei  = d_in[1];
    const void*  eli = d_in[2];
    const float* Wc1 = (const float*)d_in[3];
    const float* bc1 = (const float*)d_in[4];
    const float* Wc2 = (const float*)d_in[5];
    const float* bc2 = (const float*)d_in[6];
    const float* W1  = (const float*)d_in[7];
    const float* b1  = (const float*)d_in[8];
    const float* W2  = (const float*)d_in[9];
    const float* b2  = (const float*)d_in[10];
    float* out = (float*)d_out;

    int M = in_sizes[0] / FIN;           // 50000
    long long E  = in_sizes[1] / 2;      // 1.6M
    long long EL = in_sizes[2] / 2;      // 200K

    int smem1 = (128 * 128 + 64 * 128) * 4;
    int smem2 = (128 * 64 + 64 * 128 + 128 + 64) * 4;
    int smem3 = (64 * 128 + 64 * 64 + 64 + 64) * 4;
    cudaFuncSetAttribute(gemm1_kernel, cudaFuncAttributeMaxDynamicSharedMemorySize, smem1);
    cudaFuncSetAttribute(gemm2_kernel, cudaFuncAttributeMaxDynamicSharedMemorySize, smem2);
    cudaFuncSetAttribute(gemm3_kernel, cudaFuncAttributeMaxDynamicSharedMemorySize, smem3);

    int ntiles = (M + 63) / 64;

    zero_kernel<<<2048, 256>>>(M);
    detect_kernel<<<1, 32>>>(ei, eli, M);
    deg_kernel<<<(unsigned)((E + 255) / 256), 256>>>(ei, E);
    dinv_kernel<<<(M + 255) / 256, 256>>>(M);
    gemm1_kernel<<<ntiles, 256, smem1>>>(x, Wc1, M);
    {
        long long threads = E * 32;
        scatter1_kernel<<<(unsigned)((threads + 255) / 256), 256>>>(ei, E);
    }
    gemm2_kernel<<<ntiles, 256, smem2>>>(Wc2, bc1, M);
    {
        long long warps = (E + 1) / 2;
        long long threads = warps * 32;
        scatter2_kernel<<<(unsigned)((threads + 255) / 256), 256>>>(ei, E);
    }
    gemm3_kernel<<<ntiles, 256, smem3>>>(W1, bc2, M);
    {
        long long threads = EL * 32;
        decode_kernel<<<(unsigned)((threads + 255) / 256), 256>>>(eli, b1, W2, b2, out, EL);
    }
}

// round 5
// speedup vs baseline: 1.6399x; 1.6399x over previous
#include <cuda_runtime.h>
#include <cstdint>

#define NND 50000
#define FIN 128
#define FHID 128
#define FOUT 64
#define MAXE 1700000

// ---------------- scratch (static device allocations; no cudaMalloc) ----------------
__device__ __align__(256) float g_y1 [NND * FHID];    // (x @ Wc1) * dinv[row]
__device__ __align__(256) float g_gs1[NND * FHID];    // layer-1 neighbor gather sum
__device__ __align__(256) float g_y2 [NND * FOUT];    // (h @ Wc2) * dinv[row]
__device__ __align__(256) float g_gs2[NND * FOUT];    // layer-2 neighbor gather sum
__device__ __align__(256) float g_AB [NND * 2 * FOUT];// per-node [A|B] = z @ [W1_top|W1_bot]
__device__ __align__(256) float g_dinv[NND];
__device__ __align__(256) int   g_deg [NND];
__device__ __align__(256) int   g_rowstart[NND + 1];
__device__ __align__(256) int   g_cursor[NND];
__device__ __align__(256) int   g_csrc[MAXE];         // CSR: src ids grouped by dst
__device__ __align__(256) int   g_bsum[256];
__device__ __align__(256) int   g_boff[256];
__device__ int g_f64[2];   // [0]: edge_index is int64, [1]: edge_label_index is int64

// ---------------- helpers ----------------
__device__ __forceinline__ int ld_idx(const void* p, long long pos, int is64) {
    return is64 ? (int)((const long long*)p)[pos] : ((const int*)p)[pos];
}

// ---------------- small kernels ----------------
__global__ void zero_deg_kernel(int M) {
    int i = blockIdx.x * blockDim.x + threadIdx.x;
    if (i < M) g_deg[i] = 0;
}

__global__ void detect_kernel(const void* ei, const void* eli, int n_nodes) {
    if (blockIdx.x == 0 && threadIdx.x == 0) {
        const long long* a = (const long long*)ei;
        int ok = 1;
        for (int k = 0; k < 64; k++) { long long v = a[k]; if (v < 0 || v >= n_nodes) { ok = 0; break; } }
        g_f64[0] = ok;
        const long long* b = (const long long*)eli;
        ok = 1;
        for (int k = 0; k < 64; k++) { long long v = b[k]; if (v < 0 || v >= n_nodes) { ok = 0; break; } }
        g_f64[1] = ok;
    }
}

__global__ void deg_kernel(const void* ei, long long E) {
    long long e = (long long)blockIdx.x * blockDim.x + threadIdx.x;
    if (e >= E) return;
    int f = g_f64[0];
    int d = ld_idx(ei, E + e, f);
    atomicAdd(&g_deg[d], 1);
}

// ---------------- prefix sum (3-kernel: block scan, block-offset scan, apply) ----------------
#define SCAN_B 1024
__global__ void scan1_kernel(int M) {
    __shared__ int sh[SCAN_B];
    int i = blockIdx.x * SCAN_B + threadIdx.x;
    int v = (i < M) ? g_deg[i] : 0;
    sh[threadIdx.x] = v;
    __syncthreads();
    for (int off = 1; off < SCAN_B; off <<= 1) {
        int t = (threadIdx.x >= off) ? sh[threadIdx.x - off] : 0;
        __syncthreads();
        sh[threadIdx.x] += t;
        __syncthreads();
    }
    if (i < M) g_rowstart[i + 1] = sh[threadIdx.x];   // local inclusive scan
    if (threadIdx.x == SCAN_B - 1) g_bsum[blockIdx.x] = sh[SCAN_B - 1];
}

__global__ void scan2_kernel(int nb) {
    __shared__ int sh[1024];
    int t = threadIdx.x;
    int v = (t < nb) ? g_bsum[t] : 0;
    sh[t] = v;
    __syncthreads();
    for (int off = 1; off < 1024; off <<= 1) {
        int x = (t >= off) ? sh[t - off] : 0;
        __syncthreads();
        sh[t] += x;
        __syncthreads();
    }
    if (t < nb) g_boff[t] = sh[t] - v;   // exclusive offset per scan1 block
}

__global__ void scan3_kernel(int M) {
    int i = blockIdx.x * blockDim.x + threadIdx.x;
    if (i >= M) return;
    int off = g_boff[i >> 10];
    int rs = g_rowstart[i + 1] + off;
    g_rowstart[i + 1] = rs;
    int d = g_deg[i];
    g_cursor[i] = rs - d;
    g_dinv[i] = rsqrtf((float)d + 1.0f);
    if (i == 0) g_rowstart[0] = 0;
}

__global__ void fill_kernel(const void* ei, long long E) {
    long long e = (long long)blockIdx.x * blockDim.x + threadIdx.x;
    if (e >= E) return;
    int f = g_f64[0];
    int s = ld_idx(ei, e, f);
    int d = ld_idx(ei, E + e, f);
    int pos = atomicAdd(&g_cursor[d], 1);
    g_csrc[pos] = s;
}

// ---------------- GEMMs (fp32, smem-tiled, fused GCN epilogues) ----------------
// y1 = (x @ Wc1) * dinv[row]
__global__ void gemm1_kernel(const float* __restrict__ X, const float* __restrict__ W, int M) {
    extern __shared__ float sm[];
    float* Ws  = sm;               // 128*128
    float* Xs  = sm + 128 * 128;   // 64*128
    float* dvs = Xs + 64 * 128;    // 64
    for (int i = threadIdx.x; i < 128 * 128 / 4; i += blockDim.x)
        ((float4*)Ws)[i] = ((const float4*)W)[i];
    int row0 = blockIdx.x * 64;
    int rows = min(64, M - row0);
    for (int i = threadIdx.x; i < rows * 32; i += blockDim.x)
        ((float4*)Xs)[i] = ((const float4*)X)[(long long)row0 * 32 + i];
    if (threadIdx.x < rows) dvs[threadIdx.x] = g_dinv[row0 + threadIdx.x];
    __syncthreads();

    int rowg = threadIdx.x >> 4;   // 4 rows each
    int colg = threadIdx.x & 15;   // 8 cols each
    float acc[4][8];
#pragma unroll
    for (int r = 0; r < 4; r++)
#pragma unroll
        for (int c = 0; c < 8; c++) acc[r][c] = 0.f;

    const float* xb = Xs + rowg * 4 * 128;
    const float* wb = Ws + colg * 8;
#pragma unroll 4
    for (int k = 0; k < 128; k++) {
        float xr[4];
#pragma unroll
        for (int r = 0; r < 4; r++) xr[r] = xb[r * 128 + k];
        float w[8];
        *(float4*)&w[0] = *(const float4*)(wb + k * 128);
        *(float4*)&w[4] = *(const float4*)(wb + k * 128 + 4);
#pragma unroll
        for (int r = 0; r < 4; r++)
#pragma unroll
            for (int c = 0; c < 8; c++) acc[r][c] = fmaf(xr[r], w[c], acc[r][c]);
    }
#pragma unroll
    for (int r = 0; r < 4; r++) {
        int row = row0 + rowg * 4 + r;
        if (row < M) {
            float dv = dvs[rowg * 4 + r];
            float4* o = (float4*)(g_y1 + (long long)row * 128 + colg * 8);
            o[0] = make_float4(acc[r][0] * dv, acc[r][1] * dv, acc[r][2] * dv, acc[r][3] * dv);
            o[1] = make_float4(acc[r][4] * dv, acc[r][5] * dv, acc[r][6] * dv, acc[r][7] * dv);
        }
    }
}

// gather1: gs1[node] = sum over incoming edges of y1[src]   (warp per node, float4 lanes)
__global__ void gather1_kernel(int M) {
    int g = blockIdx.x * blockDim.x + threadIdx.x;
    int node = g >> 5;
    if (node >= M) return;
    int lane = g & 31;
    int beg = __ldg(&g_rowstart[node]);
    int end = __ldg(&g_rowstart[node + 1]);
    float4 acc = make_float4(0.f, 0.f, 0.f, 0.f);
    int p = beg;
    for (; p + 1 < end; p += 2) {
        int s0 = __ldg(&g_csrc[p]);
        int s1 = __ldg(&g_csrc[p + 1]);
        float4 a = ((const float4*)(g_y1 + (long long)s0 * FHID))[lane];
        float4 b = ((const float4*)(g_y1 + (long long)s1 * FHID))[lane];
        acc.x += a.x + b.x; acc.y += a.y + b.y; acc.z += a.z + b.z; acc.w += a.w + b.w;
    }
    if (p < end) {
        int s0 = __ldg(&g_csrc[p]);
        float4 a = ((const float4*)(g_y1 + (long long)s0 * FHID))[lane];
        acc.x += a.x; acc.y += a.y; acc.z += a.z; acc.w += a.w;
    }
    ((float4*)(g_gs1 + (long long)node * FHID))[lane] = acc;
}

// h = relu(dinv*(gs1 + y1) + bc1) in smem; y2 = (h @ Wc2) * dinv[row]
__global__ void gemm2_kernel(const float* __restrict__ Wc2, const float* __restrict__ bc1, int M) {
    extern __shared__ float sm[];
    float* Ws  = sm;                 // 128*64
    float* Hs  = Ws + 128 * 64;      // 64*128
    float* b1s = Hs + 64 * 128;      // 128
    float* dvs = b1s + 128;          // 64
    for (int i = threadIdx.x; i < 128 * 64 / 4; i += blockDim.x)
        ((float4*)Ws)[i] = ((const float4*)Wc2)[i];
    if (threadIdx.x < 128) b1s[threadIdx.x] = bc1[threadIdx.x];
    int row0 = blockIdx.x * 64;
    int rows = min(64, M - row0);
    if (threadIdx.x < rows) dvs[threadIdx.x] = g_dinv[row0 + threadIdx.x];
    __syncthreads();

    for (int i = threadIdx.x; i < rows * 32; i += blockDim.x) {
        int r = i >> 5, c = i & 31;
        float dv = dvs[r];
        float4 a = ((const float4*)g_gs1)[(long long)(row0 + r) * 32 + c];
        float4 x = ((const float4*)g_y1)[(long long)(row0 + r) * 32 + c];
        float4 h;
        h.x = fmaxf(fmaf(dv, a.x + x.x, b1s[c * 4 + 0]), 0.f);
        h.y = fmaxf(fmaf(dv, a.y + x.y, b1s[c * 4 + 1]), 0.f);
        h.z = fmaxf(fmaf(dv, a.z + x.z, b1s[c * 4 + 2]), 0.f);
        h.w = fmaxf(fmaf(dv, a.w + x.w, b1s[c * 4 + 3]), 0.f);
        ((float4*)Hs)[i] = h;
    }
    __syncthreads();

    int rowg = threadIdx.x >> 4;   // 4 rows each
    int colg = threadIdx.x & 15;   // 4 cols each
    float acc[4][4];
#pragma unroll
    for (int r = 0; r < 4; r++)
#pragma unroll
        for (int c = 0; c < 4; c++) acc[r][c] = 0.f;
    const float* xb = Hs + rowg * 4 * 128;
    const float* wb = Ws + colg * 4;
#pragma unroll 4
    for (int k = 0; k < 128; k++) {
        float xr[4];
#pragma unroll
        for (int r = 0; r < 4; r++) xr[r] = xb[r * 128 + k];
        float4 w = *(const float4*)(wb + k * 64);
#pragma unroll
        for (int r = 0; r < 4; r++) {
            acc[r][0] = fmaf(xr[r], w.x, acc[r][0]);
            acc[r][1] = fmaf(xr[r], w.y, acc[r][1]);
            acc[r][2] = fmaf(xr[r], w.z, acc[r][2]);
            acc[r][3] = fmaf(xr[r], w.w, acc[r][3]);
        }
    }
#pragma unroll
    for (int r = 0; r < 4; r++) {
        int row = row0 + rowg * 4 + r;
        if (row < M) {
            float dv = dvs[rowg * 4 + r];
            *(float4*)(g_y2 + (long long)row * 64 + colg * 4) =
                make_float4(acc[r][0] * dv, acc[r][1] * dv, acc[r][2] * dv, acc[r][3] * dv);
        }
    }
}

// gather2: gs2[node] = sum of y2[src]   (warp per node; 2 neighbors in flight, 16 lanes each)
__global__ void gather2_kernel(int M) {
    int g = blockIdx.x * blockDim.x + threadIdx.x;
    int node = g >> 5;
    if (node >= M) return;
    int lane = g & 31;
    int half = lane >> 4;
    int l = lane & 15;
    int beg = __ldg(&g_rowstart[node]);
    int end = __ldg(&g_rowstart[node + 1]);
    float4 acc = make_float4(0.f, 0.f, 0.f, 0.f);
    for (int p = beg + half; p < end; p += 2) {
        int s = __ldg(&g_csrc[p]);
        float4 a = ((const float4*)(g_y2 + (long long)s * FOUT))[l];
        acc.x += a.x; acc.y += a.y; acc.z += a.z; acc.w += a.w;
    }
    acc.x += __shfl_xor_sync(0xffffffffu, acc.x, 16);
    acc.y += __shfl_xor_sync(0xffffffffu, acc.y, 16);
    acc.z += __shfl_xor_sync(0xffffffffu, acc.z, 16);
    acc.w += __shfl_xor_sync(0xffffffffu, acc.w, 16);
    if (half == 0)
        ((float4*)(g_gs2 + (long long)node * FOUT))[l] = acc;
}

// z = dinv*(gs2 + y2) + bc2 in smem; AB = z @ W1r  ([M,64]@[64,128])
__global__ void gemm3_kernel(const float* __restrict__ W1, const float* __restrict__ bc2, int M) {
    extern __shared__ float sm[];
    float* Ws  = sm;               // 64*128 (rearranged W1)
    float* Zs  = Ws + 64 * 128;    // 64*64
    float* b2s = Zs + 64 * 64;     // 64
    float* dvs = b2s + 64;         // 64
    for (int i = threadIdx.x; i < 64 * 128; i += blockDim.x) {
        int k = i >> 7, c = i & 127;
        Ws[i] = (c < 64) ? W1[k * 64 + c] : W1[(64 + k) * 64 + (c - 64)];
    }
    if (threadIdx.x < 64) b2s[threadIdx.x] = bc2[threadIdx.x];
    int row0 = blockIdx.x * 64;
    int rows = min(64, M - row0);
    if (threadIdx.x < rows) dvs[threadIdx.x] = g_dinv[row0 + threadIdx.x];
    __syncthreads();

    for (int i = threadIdx.x; i < rows * 16; i += blockDim.x) {
        int r = i >> 4, c = i & 15;
        float dv = dvs[r];
        float4 a = ((const float4*)g_gs2)[(long long)(row0 + r) * 16 + c];
        float4 x = ((const float4*)g_y2)[(long long)(row0 + r) * 16 + c];
        float4 z;
        z.x = fmaf(dv, a.x + x.x, b2s[c * 4 + 0]);
        z.y = fmaf(dv, a.y + x.y, b2s[c * 4 + 1]);
        z.z = fmaf(dv, a.z + x.z, b2s[c * 4 + 2]);
        z.w = fmaf(dv, a.w + x.w, b2s[c * 4 + 3]);
        ((float4*)Zs)[i] = z;
    }
    __syncthreads();

    int rowg = threadIdx.x >> 4;   // 4 rows
    int colg = threadIdx.x & 15;   // 8 cols
    float acc[4][8];
#pragma unroll
    for (int r = 0; r < 4; r++)
#pragma unroll
        for (int c = 0; c < 8; c++) acc[r][c] = 0.f;
    const float* xb = Zs + rowg * 4 * 64;
    const float* wb = Ws + colg * 8;
#pragma unroll 4
    for (int k = 0; k < 64; k++) {
        float xr[4];
#pragma unroll
        for (int r = 0; r < 4; r++) xr[r] = xb[r * 64 + k];
        float w[8];
        *(float4*)&w[0] = *(const float4*)(wb + k * 128);
        *(float4*)&w[4] = *(const float4*)(wb + k * 128 + 4);
#pragma unroll
        for (int r = 0; r < 4; r++)
#pragma unroll
            for (int c = 0; c < 8; c++) acc[r][c] = fmaf(xr[r], w[c], acc[r][c]);
    }
#pragma unroll
    for (int r = 0; r < 4; r++) {
        int row = row0 + rowg * 4 + r;
        if (row < M) {
            float4* o = (float4*)(g_AB + (long long)row * 128 + colg * 8);
            o[0] = make_float4(acc[r][0], acc[r][1], acc[r][2], acc[r][3]);
            o[1] = make_float4(acc[r][4], acc[r][5], acc[r][6], acc[r][7]);
        }
    }
}

// decode: warp per label edge
__global__ void decode_kernel(const void* eli, const float* __restrict__ b1,
                              const float* __restrict__ W2, const float* __restrict__ b2,
                              float* __restrict__ out, long long EL) {
    long long g = (long long)blockIdx.x * blockDim.x + threadIdx.x;
    long long e = g >> 5;
    if (e >= EL) return;
    int lane = threadIdx.x & 31;
    int f = g_f64[1];
    int i = ld_idx(eli, e, f);
    int j = ld_idx(eli, EL + e, f);
    const float* zi = g_AB + (long long)i * 128;
    const float* zj = g_AB + (long long)j * 128;
    int c0 = lane, c1 = lane + 32;
    float b1a = __ldg(b1 + c0), b1b = __ldg(b1 + c1);
    float w2a = __ldg(W2 + c0), w2b = __ldg(W2 + c1);
    float Aia = zi[c0], Aib = zi[c1], Bia = zi[64 + c0], Bib = zi[64 + c1];
    float Aja = zj[c0], Ajb = zj[c1], Bja = zj[64 + c0], Bjb = zj[64 + c1];
    float s = fmaxf(Aia + Bja + b1a, 0.f) * w2a + fmaxf(Aib + Bjb + b1b, 0.f) * w2b
            + fmaxf(Aja + Bia + b1a, 0.f) * w2a + fmaxf(Ajb + Bib + b1b, 0.f) * w2b;
#pragma unroll
    for (int o = 16; o; o >>= 1) s += __shfl_xor_sync(0xffffffffu, s, o);
    if (lane == 0) {
        float o1 = 0.5f * s + __ldg(b2);
        out[e]      = -o1;
        out[EL + e] =  o1;
    }
}

// ---------------- launch ----------------
extern "C" void kernel_launch(void* const* d_in, const int* in_sizes, int n_in,
                              void* d_out, int out_size) {
    const float* x   = (const float*)d_in[0];
    const void*  ei  = d_in[1];
    const void*  eli = d_in[2];
    const float* Wc1 = (const float*)d_in[3];
    const float* bc1 = (const float*)d_in[4];
    const float* Wc2 = (const float*)d_in[5];
    const float* bc2 = (const float*)d_in[6];
    const float* W1  = (const float*)d_in[7];
    const float* b1  = (const float*)d_in[8];
    const float* W2  = (const float*)d_in[9];
    const float* b2  = (const float*)d_in[10];
    float* out = (float*)d_out;

    int M = in_sizes[0] / FIN;           // 50000
    long long E  = in_sizes[1] / 2;      // 1.6M
    long long EL = in_sizes[2] / 2;      // 200K

    int smem1 = (128 * 128 + 64 * 128 + 64) * 4;
    int smem2 = (128 * 64 + 64 * 128 + 128 + 64) * 4;
    int smem3 = (64 * 128 + 64 * 64 + 64 + 64) * 4;
    cudaFuncSetAttribute(gemm1_kernel, cudaFuncAttributeMaxDynamicSharedMemorySize, smem1);
    cudaFuncSetAttribute(gemm2_kernel, cudaFuncAttributeMaxDynamicSharedMemorySize, smem2);
    cudaFuncSetAttribute(gemm3_kernel, cudaFuncAttributeMaxDynamicSharedMemorySize, smem3);

    int ntiles = (M + 63) / 64;
    int nb = (M + SCAN_B - 1) / SCAN_B;

    zero_deg_kernel<<<(M + 255) / 256, 256>>>(M);
    detect_kernel<<<1, 32>>>(ei, eli, M);
    deg_kernel<<<(unsigned)((E + 255) / 256), 256>>>(ei, E);
    scan1_kernel<<<nb, SCAN_B>>>(M);
    scan2_kernel<<<1, 1024>>>(nb);
    scan3_kernel<<<(M + 255) / 256, 256>>>(M);
    fill_kernel<<<(unsigned)((E + 255) / 256), 256>>>(ei, E);
    gemm1_kernel<<<ntiles, 256, smem1>>>(x, Wc1, M);
    gather1_kernel<<<(M * 32 + 255) / 256, 256>>>(M);
    gemm2_kernel<<<ntiles, 256, smem2>>>(Wc2, bc1, M);
    gather2_kernel<<<(M * 32 + 255) / 256, 256>>>(M);
    gemm3_kernel<<<ntiles, 256, smem3>>>(W1, bc2, M);
    decode_kernel<<<(unsigned)((EL * 32 + 255) / 256), 256>>>(eli, b1, W2, b2, out, EL);
}

// round 7
// speedup vs baseline: 1.6493x; 1.0057x over previous
#include <cuda_runtime.h>
#include <cstdint>

#define NND 50000
#define FIN 128
#define FHID 128
#define FOUT 64
#define MAXE 1700000

// ---------------- scratch (static device allocations; no cudaMalloc) ----------------
__device__ __align__(256) float g_y1 [NND * FHID];    // (x @ Wc1) * dinv[row]
__device__ __align__(256) float g_gs1[NND * FHID];    // layer-1 neighbor gather sum
__device__ __align__(256) float g_y2 [NND * FOUT];    // (h @ Wc2) * dinv[row]
__device__ __align__(256) float g_gs2[NND * FOUT];    // layer-2 neighbor gather sum
__device__ __align__(256) float g_AB [NND * 2 * FOUT];// per-node [A|B] = z @ [W1_top|W1_bot]
__device__ __align__(256) float g_dinv[NND];
__device__ __align__(256) int   g_deg [NND];
__device__ __align__(256) int   g_rowstart[NND + 1];
__device__ __align__(256) int   g_cursor[NND];
__device__ __align__(256) int   g_csrc[MAXE];         // CSR: src ids grouped by dst
__device__ __align__(256) int   g_bsum[256];
__device__ __align__(256) int   g_boff[256];
__device__ int g_f64[2];   // [0]: edge_index is int64, [1]: edge_label_index is int64

// ---------------- helpers ----------------
__device__ __forceinline__ int ld_idx(const void* p, long long pos, int is64) {
    return is64 ? (int)((const long long*)p)[pos] : ((const int*)p)[pos];
}

// Blackwell packed dual-lane fp32 FMA (PTX ISA 8.6, sm_100+; not 'a'-gated)
__device__ __forceinline__ unsigned long long fma2(unsigned long long a, unsigned long long b,
                                                   unsigned long long c) {
    unsigned long long d;
    asm("fma.rn.f32x2 %0, %1, %2, %3;" : "=l"(d) : "l"(a), "l"(b), "l"(c));
    return d;
}
__device__ __forceinline__ unsigned long long pack2(float x) {
    unsigned long long d;
    asm("mov.b64 %0, {%1, %1};" : "=l"(d) : "f"(x));
    return d;
}
__device__ __forceinline__ void unpack2(unsigned long long v, float& lo, float& hi) {
    asm("mov.b64 {%0, %1}, %2;" : "=f"(lo), "=f"(hi) : "l"(v));
}

// ---------------- small kernels ----------------
__global__ void zero_deg_kernel(int M) {
    int i = blockIdx.x * blockDim.x + threadIdx.x;
    if (i < M) g_deg[i] = 0;
}

__global__ void detect_kernel(const void* ei, const void* eli, int n_nodes) {
    if (blockIdx.x == 0 && threadIdx.x == 0) {
        const long long* a = (const long long*)ei;
        int ok = 1;
        for (int k = 0; k < 64; k++) { long long v = a[k]; if (v < 0 || v >= n_nodes) { ok = 0; break; } }
        g_f64[0] = ok;
        const long long* b = (const long long*)eli;
        ok = 1;
        for (int k = 0; k < 64; k++) { long long v = b[k]; if (v < 0 || v >= n_nodes) { ok = 0; break; } }
        g_f64[1] = ok;
    }
}

__global__ void deg_kernel(const void* ei, long long E) {
    long long e = (long long)blockIdx.x * blockDim.x + threadIdx.x;
    if (e >= E) return;
    int f = g_f64[0];
    int d = ld_idx(ei, E + e, f);
    atomicAdd(&g_deg[d], 1);
}

// ---------------- prefix sum ----------------
#define SCAN_B 1024
__global__ void scan1_kernel(int M) {
    __shared__ int sh[SCAN_B];
    int i = blockIdx.x * SCAN_B + threadIdx.x;
    int v = (i < M) ? g_deg[i] : 0;
    sh[threadIdx.x] = v;
    __syncthreads();
    for (int off = 1; off < SCAN_B; off <<= 1) {
        int t = (threadIdx.x >= off) ? sh[threadIdx.x - off] : 0;
        __syncthreads();
        sh[threadIdx.x] += t;
        __syncthreads();
    }
    if (i < M) g_rowstart[i + 1] = sh[threadIdx.x];
    if (threadIdx.x == SCAN_B - 1) g_bsum[blockIdx.x] = sh[SCAN_B - 1];
}

__global__ void scan2_kernel(int nb) {
    __shared__ int sh[1024];
    int t = threadIdx.x;
    int v = (t < nb) ? g_bsum[t] : 0;
    sh[t] = v;
    __syncthreads();
    for (int off = 1; off < 1024; off <<= 1) {
        int x = (t >= off) ? sh[t - off] : 0;
        __syncthreads();
        sh[t] += x;
        __syncthreads();
    }
    if (t < nb) g_boff[t] = sh[t] - v;
}

__global__ void scan3_kernel(int M) {
    int i = blockIdx.x * blockDim.x + threadIdx.x;
    if (i >= M) return;
    int off = g_boff[i >> 10];
    int rs = g_rowstart[i + 1] + off;
    g_rowstart[i + 1] = rs;
    int d = g_deg[i];
    g_cursor[i] = rs - d;
    g_dinv[i] = rsqrtf((float)d + 1.0f);
    if (i == 0) g_rowstart[0] = 0;
}

__global__ void fill_kernel(const void* ei, long long E) {
    long long e = (long long)blockIdx.x * blockDim.x + threadIdx.x;
    if (e >= E) return;
    int f = g_f64[0];
    int s = ld_idx(ei, e, f);
    int d = ld_idx(ei, E + e, f);
    int pos = atomicAdd(&g_cursor[d], 1);
    g_csrc[pos] = s;
}

// ---------------- GEMMs (fp32 via packed f32x2 FMA, smem-tiled, fused epilogues) ----------------
// y1 = (x @ Wc1) * dinv[row]   [M,128]@[128,128]
__global__ void gemm1_kernel(const float* __restrict__ X, const float* __restrict__ W, int M) {
    extern __shared__ float sm[];
    float* Ws  = sm;               // 128*128
    float* Xs  = sm + 128 * 128;   // 64*128
    float* dvs = Xs + 64 * 128;    // 64
    for (int i = threadIdx.x; i < 128 * 128 / 4; i += blockDim.x)
        ((float4*)Ws)[i] = ((const float4*)W)[i];
    int row0 = blockIdx.x * 64;
    int rows = min(64, M - row0);
    for (int i = threadIdx.x; i < rows * 32; i += blockDim.x)
        ((float4*)Xs)[i] = ((const float4*)X)[(long long)row0 * 32 + i];
    if (threadIdx.x < rows) dvs[threadIdx.x] = g_dinv[row0 + threadIdx.x];
    __syncthreads();

    int rowg = threadIdx.x >> 4;   // 4 rows each
    int colg = threadIdx.x & 15;   // 8 cols each (4 f32x2 pairs)
    unsigned long long acc[4][4];
#pragma unroll
    for (int r = 0; r < 4; r++)
#pragma unroll
        for (int c = 0; c < 4; c++) acc[r][c] = 0ull;

    const float* xb = Xs + rowg * 4 * 128;
    const float* wb = Ws + colg * 8;
#pragma unroll 4
    for (int k = 0; k < 128; k++) {
        unsigned long long xp[4];
#pragma unroll
        for (int r = 0; r < 4; r++) xp[r] = pack2(xb[r * 128 + k]);
        float4 w0 = *(const float4*)(wb + k * 128);
        float4 w1 = *(const float4*)(wb + k * 128 + 4);
        unsigned long long wp[4];
        wp[0] = *(unsigned long long*)&w0.x;
        wp[1] = *(unsigned long long*)&w0.z;
        wp[2] = *(unsigned long long*)&w1.x;
        wp[3] = *(unsigned long long*)&w1.z;
#pragma unroll
        for (int r = 0; r < 4; r++)
#pragma unroll
            for (int c = 0; c < 4; c++) acc[r][c] = fma2(xp[r], wp[c], acc[r][c]);
    }
#pragma unroll
    for (int r = 0; r < 4; r++) {
        int row = row0 + rowg * 4 + r;
        if (row < M) {
            unsigned long long dv2 = pack2(dvs[rowg * 4 + r]);
            unsigned long long o0 = fma2(acc[r][0], dv2, 0ull);
            unsigned long long o1 = fma2(acc[r][1], dv2, 0ull);
            unsigned long long o2 = fma2(acc[r][2], dv2, 0ull);
            unsigned long long o3 = fma2(acc[r][3], dv2, 0ull);
            unsigned long long* o = (unsigned long long*)(g_y1 + (long long)row * 128 + colg * 8);
            o[0] = o0; o[1] = o1; o[2] = o2; o[3] = o3;
        }
    }
}

// gather1: gs1[node] = sum over incoming edges of y1[src]   (warp per node, float4 lanes)
__global__ void gather1_kernel(int M) {
    int g = blockIdx.x * blockDim.x + threadIdx.x;
    int node = g >> 5;
    if (node >= M) return;
    int lane = g & 31;
    int beg = __ldg(&g_rowstart[node]);
    int end = __ldg(&g_rowstart[node + 1]);
    float4 acc = make_float4(0.f, 0.f, 0.f, 0.f);
    int p = beg;
    for (; p + 1 < end; p += 2) {
        int s0 = __ldg(&g_csrc[p]);
        int s1 = __ldg(&g_csrc[p + 1]);
        float4 a = ((const float4*)(g_y1 + (long long)s0 * FHID))[lane];
        float4 b = ((const float4*)(g_y1 + (long long)s1 * FHID))[lane];
        acc.x += a.x + b.x; acc.y += a.y + b.y; acc.z += a.z + b.z; acc.w += a.w + b.w;
    }
    if (p < end) {
        int s0 = __ldg(&g_csrc[p]);
        float4 a = ((const float4*)(g_y1 + (long long)s0 * FHID))[lane];
        acc.x += a.x; acc.y += a.y; acc.z += a.z; acc.w += a.w;
    }
    ((float4*)(g_gs1 + (long long)node * FHID))[lane] = acc;
}

// h = relu(dinv*(gs1 + y1) + bc1) in smem; y2 = (h @ Wc2) * dinv[row]   [M,128]@[128,64]
__global__ void gemm2_kernel(const float* __restrict__ Wc2, const float* __restrict__ bc1, int M) {
    extern __shared__ float sm[];
    float* Ws  = sm;                 // 128*64
    float* Hs  = Ws + 128 * 64;      // 64*128
    float* b1s = Hs + 64 * 128;      // 128
    float* dvs = b1s + 128;          // 64
    for (int i = threadIdx.x; i < 128 * 64 / 4; i += blockDim.x)
        ((float4*)Ws)[i] = ((const float4*)Wc2)[i];
    if (threadIdx.x < 128) b1s[threadIdx.x] = bc1[threadIdx.x];
    int row0 = blockIdx.x * 64;
    int rows = min(64, M - row0);
    if (threadIdx.x < rows) dvs[threadIdx.x] = g_dinv[row0 + threadIdx.x];
    __syncthreads();

    for (int i = threadIdx.x; i < rows * 32; i += blockDim.x) {
        int r = i >> 5, c = i & 31;
        float dv = dvs[r];
        float4 a = ((const float4*)g_gs1)[(long long)(row0 + r) * 32 + c];
        float4 x = ((const float4*)g_y1)[(long long)(row0 + r) * 32 + c];
        float4 h;
        h.x = fmaxf(fmaf(dv, a.x + x.x, b1s[c * 4 + 0]), 0.f);
        h.y = fmaxf(fmaf(dv, a.y + x.y, b1s[c * 4 + 1]), 0.f);
        h.z = fmaxf(fmaf(dv, a.z + x.z, b1s[c * 4 + 2]), 0.f);
        h.w = fmaxf(fmaf(dv, a.w + x.w, b1s[c * 4 + 3]), 0.f);
        ((float4*)Hs)[i] = h;
    }
    __syncthreads();

    int rowg = threadIdx.x >> 4;   // 4 rows each
    int colg = threadIdx.x & 15;   // 4 cols each (2 f32x2 pairs)
    unsigned long long acc[4][2];
#pragma unroll
    for (int r = 0; r < 4; r++) { acc[r][0] = 0ull; acc[r][1] = 0ull; }
    const float* xb = Hs + rowg * 4 * 128;
    const float* wb = Ws + colg * 4;
#pragma unroll 4
    for (int k = 0; k < 128; k++) {
        unsigned long long xp[4];
#pragma unroll
        for (int r = 0; r < 4; r++) xp[r] = pack2(xb[r * 128 + k]);
        float4 w = *(const float4*)(wb + k * 64);
        unsigned long long wp0 = *(unsigned long long*)&w.x;
        unsigned long long wp1 = *(unsigned long long*)&w.z;
#pragma unroll
        for (int r = 0; r < 4; r++) {
            acc[r][0] = fma2(xp[r], wp0, acc[r][0]);
            acc[r][1] = fma2(xp[r], wp1, acc[r][1]);
        }
    }
#pragma unroll
    for (int r = 0; r < 4; r++) {
        int row = row0 + rowg * 4 + r;
        if (row < M) {
            unsigned long long dv2 = pack2(dvs[rowg * 4 + r]);
            unsigned long long o0 = fma2(acc[r][0], dv2, 0ull);
            unsigned long long o1 = fma2(acc[r][1], dv2, 0ull);
            unsigned long long* o = (unsigned long long*)(g_y2 + (long long)row * 64 + colg * 4);
            o[0] = o0; o[1] = o1;
        }
    }
}

// gather2: gs2[node] = sum of y2[src]
__global__ void gather2_kernel(int M) {
    int g = blockIdx.x * blockDim.x + threadIdx.x;
    int node = g >> 5;
    if (node >= M) return;
    int lane = g & 31;
    int half = lane >> 4;
    int l = lane & 15;
    int beg = __ldg(&g_rowstart[node]);
    int end = __ldg(&g_rowstart[node + 1]);
    float4 acc = make_float4(0.f, 0.f, 0.f, 0.f);
    for (int p = beg + half; p < end; p += 2) {
        int s = __ldg(&g_csrc[p]);
        float4 a = ((const float4*)(g_y2 + (long long)s * FOUT))[l];
        acc.x += a.x; acc.y += a.y; acc.z += a.z; acc.w += a.w;
    }
    acc.x += __shfl_xor_sync(0xffffffffu, acc.x, 16);
    acc.y += __shfl_xor_sync(0xffffffffu, acc.y, 16);
    acc.z += __shfl_xor_sync(0xffffffffu, acc.z, 16);
    acc.w += __shfl_xor_sync(0xffffffffu, acc.w, 16);
    if (half == 0)
        ((float4*)(g_gs2 + (long long)node * FOUT))[l] = acc;
}

// z = dinv*(gs2 + y2) + bc2 in smem; AB = z @ W1r   [M,64]@[64,128]
__global__ void gemm3_kernel(const float* __restrict__ W1, const float* __restrict__ bc2, int M) {
    extern __shared__ float sm[];
    float* Ws  = sm;               // 64*128 (rearranged W1)
    float* Zs  = Ws + 64 * 128;    // 64*64
    float* b2s = Zs + 64 * 64;     // 64
    float* dvs = b2s + 64;         // 64
    for (int i = threadIdx.x; i < 64 * 128; i += blockDim.x) {
        int k = i >> 7, c = i & 127;
        Ws[i] = (c < 64) ? W1[k * 64 + c] : W1[(64 + k) * 64 + (c - 64)];
    }
    if (threadIdx.x < 64) b2s[threadIdx.x] = bc2[threadIdx.x];
    int row0 = blockIdx.x * 64;
    int rows = min(64, M - row0);
    if (threadIdx.x < rows) dvs[threadIdx.x] = g_dinv[row0 + threadIdx.x];
    __syncthreads();

    for (int i = threadIdx.x; i < rows * 16; i += blockDim.x) {
        int r = i >> 4, c = i & 15;
        float dv = dvs[r];
        float4 a = ((const float4*)g_gs2)[(long long)(row0 + r) * 16 + c];
        float4 x = ((const float4*)g_y2)[(long long)(row0 + r) * 16 + c];
        float4 z;
        z.x = fmaf(dv, a.x + x.x, b2s[c * 4 + 0]);
        z.y = fmaf(dv, a.y + x.y, b2s[c * 4 + 1]);
        z.z = fmaf(dv, a.z + x.z, b2s[c * 4 + 2]);
        z.w = fmaf(dv, a.w + x.w, b2s[c * 4 + 3]);
        ((float4*)Zs)[i] = z;
    }
    __syncthreads();

    int rowg = threadIdx.x >> 4;   // 4 rows
    int colg = threadIdx.x & 15;   // 8 cols (4 f32x2 pairs)
    unsigned long long acc[4][4];
#pragma unroll
    for (int r = 0; r < 4; r++)
#pragma unroll
        for (int c = 0; c < 4; c++) acc[r][c] = 0ull;
    const float* xb = Zs + rowg * 4 * 64;
    const float* wb = Ws + colg * 8;
#pragma unroll 4
    for (int k = 0; k < 64; k++) {
        unsigned long long xp[4];
#pragma unroll
        for (int r = 0; r < 4; r++) xp[r] = pack2(xb[r * 64 + k]);
        float4 w0 = *(const float4*)(wb + k * 128);
        float4 w1 = *(const float4*)(wb + k * 128 + 4);
        unsigned long long wp[4];
        wp[0] = *(unsigned long long*)&w0.x;
        wp[1] = *(unsigned long long*)&w0.z;
        wp[2] = *(unsigned long long*)&w1.x;
        wp[3] = *(unsigned long long*)&w1.z;
#pragma unroll
        for (int r = 0; r < 4; r++)
#pragma unroll
            for (int c = 0; c < 4; c++) acc[r][c] = fma2(xp[r], wp[c], acc[r][c]);
    }
#pragma unroll
    for (int r = 0; r < 4; r++) {
        int row = row0 + rowg * 4 + r;
        if (row < M) {
            unsigned long long* o = (unsigned long long*)(g_AB + (long long)row * 128 + colg * 8);
            o[0] = acc[r][0]; o[1] = acc[r][1]; o[2] = acc[r][2]; o[3] = acc[r][3];
        }
    }
}

// decode: warp per label edge
__global__ void decode_kernel(const void* eli, const float* __restrict__ b1,
                              const float* __restrict__ W2, const float* __restrict__ b2,
                              float* __restrict__ out, long long EL) {
    long long g = (long long)blockIdx.x * blockDim.x + threadIdx.x;
    long long e = g >> 5;
    if (e >= EL) return;
    int lane = threadIdx.x & 31;
    int f = g_f64[1];
    int i = ld_idx(eli, e, f);
    int j = ld_idx(eli, EL + e, f);
    const float* zi = g_AB + (long long)i * 128;
    const float* zj = g_AB + (long long)j * 128;
    int c0 = lane, c1 = lane + 32;
    float b1a = __ldg(b1 + c0), b1b = __ldg(b1 + c1);
    float w2a = __ldg(W2 + c0), w2b = __ldg(W2 + c1);
    float Aia = zi[c0], Aib = zi[c1], Bia = zi[64 + c0], Bib = zi[64 + c1];
    float Aja = zj[c0], Ajb = zj[c1], Bja = zj[64 + c0], Bjb = zj[64 + c1];
    float s = fmaxf(Aia + Bja + b1a, 0.f) * w2a + fmaxf(Aib + Bjb + b1b, 0.f) * w2b
            + fmaxf(Aja + Bia + b1a, 0.f) * w2a + fmaxf(Ajb + Bib + b1b, 0.f) * w2b;
#pragma unroll
    for (int o = 16; o; o >>= 1) s += __shfl_xor_sync(0xffffffffu, s, o);
    if (lane == 0) {
        float o1 = 0.5f * s + __ldg(b2);
        out[e]      = -o1;
        out[EL + e] =  o1;
    }
}

// ---------------- launch ----------------
extern "C" void kernel_launch(void* const* d_in, const int* in_sizes, int n_in,
                              void* d_out, int out_size) {
    const float* x   = (const float*)d_in[0];
    const void*  ei  = d_in[1];
    const void*  eli = d_in[2];
    const float* Wc1 = (const float*)d_in[3];
    const float* bc1 = (const float*)d_in[4];
    const float* Wc2 = (const float*)d_in[5];
    const float* bc2 = (const float*)d_in[6];
    const float* W1  = (const float*)d_in[7];
    const float* b1  = (const float*)d_in[8];
    const float* W2  = (const float*)d_in[9];
    const float* b2  = (const float*)d_in[10];
    float* out = (float*)d_out;

    int M = in_sizes[0] / FIN;           // 50000
    long long E  = in_sizes[1] / 2;      // 1.6M
    long long EL = in_sizes[2] / 2;      // 200K

    int smem1 = (128 * 128 + 64 * 128 + 64) * 4;
    int smem2 = (128 * 64 + 64 * 128 + 128 + 64) * 4;
    int smem3 = (64 * 128 + 64 * 64 + 64 + 64) * 4;
    cudaFuncSetAttribute(gemm1_kernel, cudaFuncAttributeMaxDynamicSharedMemorySize, smem1);
    cudaFuncSetAttribute(gemm2_kernel, cudaFuncAttributeMaxDynamicSharedMemorySize, smem2);
    cudaFuncSetAttribute(gemm3_kernel, cudaFuncAttributeMaxDynamicSharedMemorySize, smem3);

    int ntiles = (M + 63) / 64;
    int nb = (M + SCAN_B - 1) / SCAN_B;

    zero_deg_kernel<<<(M + 255) / 256, 256>>>(M);
    detect_kernel<<<1, 32>>>(ei, eli, M);
    deg_kernel<<<(unsigned)((E + 255) / 256), 256>>>(ei, E);
    scan1_kernel<<<nb, SCAN_B>>>(M);
    scan2_kernel<<<1, 1024>>>(nb);
    scan3_kernel<<<(M + 255) / 256, 256>>>(M);
    fill_kernel<<<(unsigned)((E + 255) / 256), 256>>>(ei, E);
    gemm1_kernel<<<ntiles, 256, smem1>>>(x, Wc1, M);
    gather1_kernel<<<(M * 32 + 255) / 256, 256>>>(M);
    gemm2_kernel<<<ntiles, 256, smem2>>>(Wc2, bc1, M);
    gather2_kernel<<<(M * 32 + 255) / 256, 256>>>(M);
    gemm3_kernel<<<ntiles, 256, smem3>>>(W1, bc2, M);
    decode_kernel<<<(unsigned)((EL * 32 + 255) / 256), 256>>>(eli, b1, W2, b2, out, EL);
}

// round 10
// speedup vs baseline: 1.8346x; 1.1124x over previous
#include <cuda_runtime.h>
#include <cuda_bf16.h>
#include <cstdint>

#define NND 50000
#define FIN 128
#define FHID 128
#define FOUT 64
#define MAXE 1700000

typedef unsigned short ushort_t;

// ---------------- scratch (static device allocations; no cudaMalloc) ----------------
__device__ __align__(256) float g_y1 [NND * FHID];
__device__ __align__(256) float g_gs1[NND * FHID];
__device__ __align__(256) float g_y2 [NND * FOUT];
__device__ __align__(256) float g_gs2[NND * FOUT];
__device__ __align__(256) float g_AB [NND * 2 * FOUT];
__device__ __align__(256) float g_dinv[NND];
__device__ __align__(256) int   g_deg [NND];
__device__ __align__(256) int   g_rowstart[NND + 1];
__device__ __align__(256) int   g_cursor[NND];
__device__ __align__(256) int   g_csrc[MAXE];
__device__ __align__(256) int   g_bsum[256];
__device__ __align__(256) int   g_boff[256];
__device__ int g_f64[2];

// bf16 weight images, K-concatenated hi/lo: B'[n][0:K)=Bh, [K:2K)=Bh, [2K:3K)=Bl
// pitch gemm1/2 = 392 (=384+8 pad), gemm3 = 200 (=192+8 pad)
__device__ __align__(16) ushort_t g_B1[128 * 392];   // from Wc1^T (K=128)
__device__ __align__(16) ushort_t g_B2[64 * 392];    // from Wc2^T (K=128)
__device__ __align__(16) ushort_t g_B3[128 * 200];   // from W1r^T (K=64)

// ---------------- helpers ----------------
__device__ __forceinline__ int ld_idx(const void* p, long long pos, int is64) {
    return is64 ? (int)((const long long*)p)[pos] : ((const int*)p)[pos];
}

// pack (x,y) -> bf16x2 hi word; compute residual pack too. low half = x, high half = y.
__device__ __forceinline__ void split_pair(float x, float y, uint32_t& hi, uint32_t& lo) {
    asm("cvt.rn.bf16x2.f32 %0, %1, %2;" : "=r"(hi) : "f"(y), "f"(x));
    float hx = __uint_as_float(hi << 16);
    float hy = __uint_as_float(hi & 0xFFFF0000u);
    asm("cvt.rn.bf16x2.f32 %0, %1, %2;" : "=r"(lo) : "f"(y - hy), "f"(x - hx));
}

__device__ __forceinline__ void mma16816(float* c, uint32_t a0, uint32_t a1, uint32_t a2,
                                         uint32_t a3, uint32_t b0, uint32_t b1) {
    asm("mma.sync.aligned.m16n8k16.row.col.f32.bf16.bf16.f32 "
        "{%0,%1,%2,%3}, {%4,%5,%6,%7}, {%8,%9}, {%0,%1,%2,%3};"
        : "+f"(c[0]), "+f"(c[1]), "+f"(c[2]), "+f"(c[3])
        : "r"(a0), "r"(a1), "r"(a2), "r"(a3), "r"(b0), "r"(b1));
}

// ---------------- small kernels ----------------
__global__ void zero_deg_kernel(int M) {
    int i = blockIdx.x * blockDim.x + threadIdx.x;
    if (i < M) g_deg[i] = 0;
}

__global__ void detect_kernel(const void* ei, const void* eli, int n_nodes) {
    if (blockIdx.x == 0 && threadIdx.x == 0) {
        const long long* a = (const long long*)ei;
        int ok = 1;
        for (int k = 0; k < 64; k++) { long long v = a[k]; if (v < 0 || v >= n_nodes) { ok = 0; break; } }
        g_f64[0] = ok;
        const long long* b = (const long long*)eli;
        ok = 1;
        for (int k = 0; k < 64; k++) { long long v = b[k]; if (v < 0 || v >= n_nodes) { ok = 0; break; } }
        g_f64[1] = ok;
    }
}

__global__ void deg_kernel(const void* ei, long long E) {
    long long e = (long long)blockIdx.x * blockDim.x + threadIdx.x;
    if (e >= E) return;
    int f = g_f64[0];
    int d = ld_idx(ei, E + e, f);
    atomicAdd(&g_deg[d], 1);
}

// weight prep: transpose + hi/lo split into K-concat bf16 images
__global__ void prep_kernel(const float* __restrict__ Wc1, const float* __restrict__ Wc2,
                            const float* __restrict__ W1) {
    int id = blockIdx.x * blockDim.x + threadIdx.x;
    if (id < 16384) {                      // B1: n<128, k<128
        int n = id >> 7, k = id & 127;
        float v = Wc1[k * 128 + n];
        __nv_bfloat16 hb = __float2bfloat16_rn(v);
        __nv_bfloat16 lb = __float2bfloat16_rn(v - __bfloat162float(hb));
        int base = n * 392;
        g_B1[base + k]       = __bfloat16_as_ushort(hb);
        g_B1[base + 128 + k] = __bfloat16_as_ushort(hb);
        g_B1[base + 256 + k] = __bfloat16_as_ushort(lb);
    } else if (id < 24576) {               // B2: n<64, k<128
        int t = id - 16384;
        int n = t >> 7, k = t & 127;
        float v = Wc2[k * 64 + n];
        __nv_bfloat16 hb = __float2bfloat16_rn(v);
        __nv_bfloat16 lb = __float2bfloat16_rn(v - __bfloat162float(hb));
        int base = n * 392;
        g_B2[base + k]       = __bfloat16_as_ushort(hb);
        g_B2[base + 128 + k] = __bfloat16_as_ushort(hb);
        g_B2[base + 256 + k] = __bfloat16_as_ushort(lb);
    } else if (id < 32768) {               // B3: n<128, k<64  (W1r)
        int t = id - 24576;
        int n = t >> 6, k = t & 63;
        float v = (n < 64) ? W1[k * 64 + n] : W1[(64 + k) * 64 + (n - 64)];
        __nv_bfloat16 hb = __float2bfloat16_rn(v);
        __nv_bfloat16 lb = __float2bfloat16_rn(v - __bfloat162float(hb));
        int base = n * 200;
        g_B3[base + k]       = __bfloat16_as_ushort(hb);
        g_B3[base + 64 + k]  = __bfloat16_as_ushort(hb);
        g_B3[base + 128 + k] = __bfloat16_as_ushort(lb);
    }
}

// ---------------- prefix sum ----------------
#define SCAN_B 1024
__global__ void scan1_kernel(int M) {
    __shared__ int sh[SCAN_B];
    int i = blockIdx.x * SCAN_B + threadIdx.x;
    int v = (i < M) ? g_deg[i] : 0;
    sh[threadIdx.x] = v;
    __syncthreads();
    for (int off = 1; off < SCAN_B; off <<= 1) {
        int t = (threadIdx.x >= off) ? sh[threadIdx.x - off] : 0;
        __syncthreads();
        sh[threadIdx.x] += t;
        __syncthreads();
    }
    if (i < M) g_rowstart[i + 1] = sh[threadIdx.x];
    if (threadIdx.x == SCAN_B - 1) g_bsum[blockIdx.x] = sh[SCAN_B - 1];
}

__global__ void scan2_kernel(int nb) {
    __shared__ int sh[1024];
    int t = threadIdx.x;
    int v = (t < nb) ? g_bsum[t] : 0;
    sh[t] = v;
    __syncthreads();
    for (int off = 1; off < 1024; off <<= 1) {
        int x = (t >= off) ? sh[t - off] : 0;
        __syncthreads();
        sh[t] += x;
        __syncthreads();
    }
    if (t < nb) g_boff[t] = sh[t] - v;
}

__global__ void scan3_kernel(int M) {
    int i = blockIdx.x * blockDim.x + threadIdx.x;
    if (i >= M) return;
    int off = g_boff[i >> 10];
    int rs = g_rowstart[i + 1] + off;
    g_rowstart[i + 1] = rs;
    int d = g_deg[i];
    g_cursor[i] = rs - d;
    g_dinv[i] = rsqrtf((float)d + 1.0f);
    if (i == 0) g_rowstart[0] = 0;
}

__global__ void fill_kernel(const void* ei, long long E) {
    long long e = (long long)blockIdx.x * blockDim.x + threadIdx.x;
    if (e >= E) return;
    int f = g_f64[0];
    int s = ld_idx(ei, e, f);
    int d = ld_idx(ei, E + e, f);
    int pos = atomicAdd(&g_cursor[d], 1);
    g_csrc[pos] = s;
}

// ---------------- mma GEMM 1: y1 = (x @ Wc1) * dinv   [M,128]@[128,128], K'=384 ----------------
__global__ void __launch_bounds__(256) gemm1_mma(const float* __restrict__ X, int M) {
    extern __shared__ __align__(16) char smem[];
    ushort_t* As = (ushort_t*)smem;               // 128 x 392
    ushort_t* Bs = As + 128 * 392;                // 128 x 392
    float* dvs = (float*)(Bs + 128 * 392);        // 128
    int tid = threadIdx.x;
    int row0 = blockIdx.x * 128;
    int rows = min(128, M - row0);

    for (int i = tid; i < 6272; i += 256) ((uint4*)Bs)[i] = ((const uint4*)g_B1)[i];
    if (rows < 128) {
        uint4 z = make_uint4(0, 0, 0, 0);
        for (int i = tid; i < 6272; i += 256) ((uint4*)As)[i] = z;
    }
    if (tid < 128) dvs[tid] = (row0 + tid < M) ? g_dinv[row0 + tid] : 0.f;
    if (rows < 128) __syncthreads();

    for (int idx = tid; idx < rows * 32; idx += 256) {
        int r = idx >> 5, c = idx & 31;
        float4 v = ((const float4*)(X + (size_t)(row0 + r) * 128))[c];
        uint32_t h01, l01, h23, l23;
        split_pair(v.x, v.y, h01, l01);
        split_pair(v.z, v.w, h23, l23);
        ushort_t* ar = As + r * 392 + c * 4;
        *(uint32_t*)(ar)           = h01;
        *(uint32_t*)(ar + 2)       = h23;
        *(uint32_t*)(ar + 128)     = l01;
        *(uint32_t*)(ar + 130)     = l23;
        *(uint32_t*)(ar + 256)     = h01;
        *(uint32_t*)(ar + 258)     = h23;
    }
    __syncthreads();

    int w = tid >> 5, lane = tid & 31, g = lane >> 2, tig = lane & 3;
    float acc[16][4];
#pragma unroll
    for (int t = 0; t < 16; t++)
#pragma unroll
        for (int j = 0; j < 4; j++) acc[t][j] = 0.f;

    const ushort_t* ar1 = As + (w * 16 + g) * 392;
    const ushort_t* ar2 = ar1 + 8 * 392;
    for (int ks = 0; ks < 24; ks++) {
        int kc = ks * 16 + tig * 2;
        uint32_t a0 = *(const uint32_t*)(ar1 + kc);
        uint32_t a1 = *(const uint32_t*)(ar2 + kc);
        uint32_t a2 = *(const uint32_t*)(ar1 + kc + 8);
        uint32_t a3 = *(const uint32_t*)(ar2 + kc + 8);
#pragma unroll
        for (int t = 0; t < 16; t++) {
            const ushort_t* br = Bs + (t * 8 + g) * 392 + kc;
            uint32_t b0 = *(const uint32_t*)(br);
            uint32_t b1 = *(const uint32_t*)(br + 8);
            mma16816(acc[t], a0, a1, a2, a3, b0, b1);
        }
    }

    int m1 = row0 + w * 16 + g, m2 = m1 + 8;
    float dv1 = dvs[w * 16 + g], dv2 = dvs[w * 16 + g + 8];
#pragma unroll
    for (int t = 0; t < 16; t++) {
        int c0 = t * 8 + tig * 2;
        if (m1 < M) *(float2*)(g_y1 + (size_t)m1 * 128 + c0) = make_float2(acc[t][0] * dv1, acc[t][1] * dv1);
        if (m2 < M) *(float2*)(g_y1 + (size_t)m2 * 128 + c0) = make_float2(acc[t][2] * dv2, acc[t][3] * dv2);
    }
}

// gather1
__global__ void gather1_kernel(int M) {
    int g = blockIdx.x * blockDim.x + threadIdx.x;
    int node = g >> 5;
    if (node >= M) return;
    int lane = g & 31;
    int beg = __ldg(&g_rowstart[node]);
    int end = __ldg(&g_rowstart[node + 1]);
    float4 acc = make_float4(0.f, 0.f, 0.f, 0.f);
    int p = beg;
    for (; p + 1 < end; p += 2) {
        int s0 = __ldg(&g_csrc[p]);
        int s1 = __ldg(&g_csrc[p + 1]);
        float4 a = ((const float4*)(g_y1 + (long long)s0 * FHID))[lane];
        float4 b = ((const float4*)(g_y1 + (long long)s1 * FHID))[lane];
        acc.x += a.x + b.x; acc.y += a.y + b.y; acc.z += a.z + b.z; acc.w += a.w + b.w;
    }
    if (p < end) {
        int s0 = __ldg(&g_csrc[p]);
        float4 a = ((const float4*)(g_y1 + (long long)s0 * FHID))[lane];
        acc.x += a.x; acc.y += a.y; acc.z += a.z; acc.w += a.w;
    }
    ((float4*)(g_gs1 + (long long)node * FHID))[lane] = acc;
}

// ---------------- mma GEMM 2: h=relu(dinv*(gs1+y1)+b1); y2=(h@Wc2)*dinv  [M,128]@[128,64] ----------------
__global__ void __launch_bounds__(256) gemm2_mma(const float* __restrict__ bc1, int M) {
    extern __shared__ __align__(16) char smem[];
    ushort_t* As = (ushort_t*)smem;               // 128 x 392
    ushort_t* Bs = As + 128 * 392;                // 64 x 392
    float* dvs = (float*)(Bs + 64 * 392);         // 128
    int tid = threadIdx.x;
    int row0 = blockIdx.x * 128;
    int rows = min(128, M - row0);

    for (int i = tid; i < 3136; i += 256) ((uint4*)Bs)[i] = ((const uint4*)g_B2)[i];
    if (rows < 128) {
        uint4 z = make_uint4(0, 0, 0, 0);
        for (int i = tid; i < 6272; i += 256) ((uint4*)As)[i] = z;
    }
    if (tid < 128) dvs[tid] = (row0 + tid < M) ? g_dinv[row0 + tid] : 0.f;
    __syncthreads();

    for (int idx = tid; idx < rows * 32; idx += 256) {
        int r = idx >> 5, c = idx & 31;
        float dv = dvs[r];
        float4 a = ((const float4*)g_gs1)[(long long)(row0 + r) * 32 + c];
        float4 x = ((const float4*)g_y1)[(long long)(row0 + r) * 32 + c];
        float4 bb = __ldg((const float4*)bc1 + c);
        float h0 = fmaxf(fmaf(dv, a.x + x.x, bb.x), 0.f);
        float h1 = fmaxf(fmaf(dv, a.y + x.y, bb.y), 0.f);
        float h2 = fmaxf(fmaf(dv, a.z + x.z, bb.z), 0.f);
        float h3 = fmaxf(fmaf(dv, a.w + x.w, bb.w), 0.f);
        uint32_t h01, l01, h23, l23;
        split_pair(h0, h1, h01, l01);
        split_pair(h2, h3, h23, l23);
        ushort_t* ar = As + r * 392 + c * 4;
        *(uint32_t*)(ar)       = h01;
        *(uint32_t*)(ar + 2)   = h23;
        *(uint32_t*)(ar + 128) = l01;
        *(uint32_t*)(ar + 130) = l23;
        *(uint32_t*)(ar + 256) = h01;
        *(uint32_t*)(ar + 258) = h23;
    }
    __syncthreads();

    int w = tid >> 5, lane = tid & 31, g = lane >> 2, tig = lane & 3;
    float acc[8][4];
#pragma unroll
    for (int t = 0; t < 8; t++)
#pragma unroll
        for (int j = 0; j < 4; j++) acc[t][j] = 0.f;

    const ushort_t* ar1 = As + (w * 16 + g) * 392;
    const ushort_t* ar2 = ar1 + 8 * 392;
    for (int ks = 0; ks < 24; ks++) {
        int kc = ks * 16 + tig * 2;
        uint32_t a0 = *(const uint32_t*)(ar1 + kc);
        uint32_t a1 = *(const uint32_t*)(ar2 + kc);
        uint32_t a2 = *(const uint32_t*)(ar1 + kc + 8);
        uint32_t a3 = *(const uint32_t*)(ar2 + kc + 8);
#pragma unroll
        for (int t = 0; t < 8; t++) {
            const ushort_t* br = Bs + (t * 8 + g) * 392 + kc;
            uint32_t b0 = *(const uint32_t*)(br);
            uint32_t b1 = *(const uint32_t*)(br + 8);
            mma16816(acc[t], a0, a1, a2, a3, b0, b1);
        }
    }

    int m1 = row0 + w * 16 + g, m2 = m1 + 8;
    float dv1 = dvs[w * 16 + g], dv2 = dvs[w * 16 + g + 8];
#pragma unroll
    for (int t = 0; t < 8; t++) {
        int c0 = t * 8 + tig * 2;
        if (m1 < M) *(float2*)(g_y2 + (size_t)m1 * 64 + c0) = make_float2(acc[t][0] * dv1, acc[t][1] * dv1);
        if (m2 < M) *(float2*)(g_y2 + (size_t)m2 * 64 + c0) = make_float2(acc[t][2] * dv2, acc[t][3] * dv2);
    }
}

// gather2
__global__ void gather2_kernel(int M) {
    int g = blockIdx.x * blockDim.x + threadIdx.x;
    int node = g >> 5;
    if (node >= M) return;
    int lane = g & 31;
    int half = lane >> 4;
    int l = lane & 15;
    int beg = __ldg(&g_rowstart[node]);
    int end = __ldg(&g_rowstart[node + 1]);
    float4 acc = make_float4(0.f, 0.f, 0.f, 0.f);
    for (int p = beg + half; p < end; p += 2) {
        int s = __ldg(&g_csrc[p]);
        float4 a = ((const float4*)(g_y2 + (long long)s * FOUT))[l];
        acc.x += a.x; acc.y += a.y; acc.z += a.z; acc.w += a.w;
    }
    acc.x += __shfl_xor_sync(0xffffffffu, acc.x, 16);
    acc.y += __shfl_xor_sync(0xffffffffu, acc.y, 16);
    acc.z += __shfl_xor_sync(0xffffffffu, acc.z, 16);
    acc.w += __shfl_xor_sync(0xffffffffu, acc.w, 16);
    if (half == 0)
        ((float4*)(g_gs2 + (long long)node * FOUT))[l] = acc;
}

// ---------------- mma GEMM 3: z=dinv*(gs2+y2)+b2; AB=z@W1r  [M,64]@[64,128], K'=192 ----------------
__global__ void __launch_bounds__(256) gemm3_mma(const float* __restrict__ bc2, int M) {
    extern __shared__ __align__(16) char smem[];
    ushort_t* As = (ushort_t*)smem;               // 128 x 200
    ushort_t* Bs = As + 128 * 200;                // 128 x 200
    float* dvs = (float*)(Bs + 128 * 200);        // 128
    int tid = threadIdx.x;
    int row0 = blockIdx.x * 128;
    int rows = min(128, M - row0);

    for (int i = tid; i < 3200; i += 256) ((uint4*)Bs)[i] = ((const uint4*)g_B3)[i];
    if (rows < 128) {
        uint4 z = make_uint4(0, 0, 0, 0);
        for (int i = tid; i < 3200; i += 256) ((uint4*)As)[i] = z;
    }
    if (tid < 128) dvs[tid] = (row0 + tid < M) ? g_dinv[row0 + tid] : 0.f;
    __syncthreads();

    for (int idx = tid; idx < rows * 16; idx += 256) {
        int r = idx >> 4, c = idx & 15;
        float dv = dvs[r];
        float4 a = ((const float4*)g_gs2)[(long long)(row0 + r) * 16 + c];
        float4 x = ((const float4*)g_y2)[(long long)(row0 + r) * 16 + c];
        float4 bb = __ldg((const float4*)bc2 + c);
        float z0 = fmaf(dv, a.x + x.x, bb.x);
        float z1 = fmaf(dv, a.y + x.y, bb.y);
        float z2 = fmaf(dv, a.z + x.z, bb.z);
        float z3 = fmaf(dv, a.w + x.w, bb.w);
        uint32_t h01, l01, h23, l23;
        split_pair(z0, z1, h01, l01);
        split_pair(z2, z3, h23, l23);
        ushort_t* ar = As + r * 200 + c * 4;
        *(uint32_t*)(ar)       = h01;
        *(uint32_t*)(ar + 2)   = h23;
        *(uint32_t*)(ar + 64)  = l01;
        *(uint32_t*)(ar + 66)  = l23;
        *(uint32_t*)(ar + 128) = h01;
        *(uint32_t*)(ar + 130) = h23;
    }
    __syncthreads();

    int w = tid >> 5, lane = tid & 31, g = lane >> 2, tig = lane & 3;
    float acc[16][4];
#pragma unroll
    for (int t = 0; t < 16; t++)
#pragma unroll
        for (int j = 0; j < 4; j++) acc[t][j] = 0.f;

    const ushort_t* ar1 = As + (w * 16 + g) * 200;
    const ushort_t* ar2 = ar1 + 8 * 200;
    for (int ks = 0; ks < 12; ks++) {
        int kc = ks * 16 + tig * 2;
        uint32_t a0 = *(const uint32_t*)(ar1 + kc);
        uint32_t a1 = *(const uint32_t*)(ar2 + kc);
        uint32_t a2 = *(const uint32_t*)(ar1 + kc + 8);
        uint32_t a3 = *(const uint32_t*)(ar2 + kc + 8);
#pragma unroll
        for (int t = 0; t < 16; t++) {
            const ushort_t* br = Bs + (t * 8 + g) * 200 + kc;
            uint32_t b0 = *(const uint32_t*)(br);
            uint32_t b1 = *(const uint32_t*)(br + 8);
            mma16816(acc[t], a0, a1, a2, a3, b0, b1);
        }
    }

    int m1 = row0 + w * 16 + g, m2 = m1 + 8;
#pragma unroll
    for (int t = 0; t < 16; t++) {
        int c0 = t * 8 + tig * 2;
        if (m1 < M) *(float2*)(g_AB + (size_t)m1 * 128 + c0) = make_float2(acc[t][0], acc[t][1]);
        if (m2 < M) *(float2*)(g_AB + (size_t)m2 * 128 + c0) = make_float2(acc[t][2], acc[t][3]);
    }
}

// decode: warp per label edge
__global__ void decode_kernel(const void* eli, const float* __restrict__ b1,
                              const float* __restrict__ W2, const float* __restrict__ b2,
                              float* __restrict__ out, long long EL) {
    long long g = (long long)blockIdx.x * blockDim.x + threadIdx.x;
    long long e = g >> 5;
    if (e >= EL) return;
    int lane = threadIdx.x & 31;
    int f = g_f64[1];
    int i = ld_idx(eli, e, f);
    int j = ld_idx(eli, EL + e, f);
    const float* zi = g_AB + (long long)i * 128;
    const float* zj = g_AB + (long long)j * 128;
    int c0 = lane, c1 = lane + 32;
    float b1a = __ldg(b1 + c0), b1b = __ldg(b1 + c1);
    float w2a = __ldg(W2 + c0), w2b = __ldg(W2 + c1);
    float Aia = zi[c0], Aib = zi[c1], Bia = zi[64 + c0], Bib = zi[64 + c1];
    float Aja = zj[c0], Ajb = zj[c1], Bja = zj[64 + c0], Bjb = zj[64 + c1];
    float s = fmaxf(Aia + Bja + b1a, 0.f) * w2a + fmaxf(Aib + Bjb + b1b, 0.f) * w2b
            + fmaxf(Aja + Bia + b1a, 0.f) * w2a + fmaxf(Ajb + Bib + b1b, 0.f) * w2b;
#pragma unroll
    for (int o = 16; o; o >>= 1) s += __shfl_xor_sync(0xffffffffu, s, o);
    if (lane == 0) {
        float o1 = 0.5f * s + __ldg(b2);
        out[e]      = -o1;
        out[EL + e] =  o1;
    }
}

// ---------------- launch ----------------
extern "C" void kernel_launch(void* const* d_in, const int* in_sizes, int n_in,
                              void* d_out, int out_size) {
    const float* x   = (const float*)d_in[0];
    const void*  ei  = d_in[1];
    const void*  eli = d_in[2];
    const float* Wc1 = (const float*)d_in[3];
    const float* bc1 = (const float*)d_in[4];
    const float* Wc2 = (const float*)d_in[5];
    const float* bc2 = (const float*)d_in[6];
    const float* W1  = (const float*)d_in[7];
    const float* b1  = (const float*)d_in[8];
    const float* W2  = (const float*)d_in[9];
    const float* b2  = (const float*)d_in[10];
    float* out = (float*)d_out;

    int M = in_sizes[0] / FIN;           // 50000
    long long E  = in_sizes[1] / 2;      // 1.6M
    long long EL = in_sizes[2] / 2;      // 200K

    int smem1 = (128 * 392 + 128 * 392) * 2 + 512;   // 201,216
    int smem2 = (128 * 392 + 64 * 392) * 2 + 512;    // 151,040
    int smem3 = (128 * 200 + 128 * 200) * 2 + 512;   // 102,912
    cudaFuncSetAttribute(gemm1_mma, cudaFuncAttributeMaxDynamicSharedMemorySize, smem1);
    cudaFuncSetAttribute(gemm2_mma, cudaFuncAttributeMaxDynamicSharedMemorySize, smem2);
    cudaFuncSetAttribute(gemm3_mma, cudaFuncAttributeMaxDynamicSharedMemorySize, smem3);

    int ntiles = (M + 127) / 128;
    int nb = (M + SCAN_B - 1) / SCAN_B;

    zero_deg_kernel<<<(M + 255) / 256, 256>>>(M);
    detect_kernel<<<1, 32>>>(ei, eli, M);
    prep_kernel<<<128, 256>>>(Wc1, Wc2, W1);
    deg_kernel<<<(unsigned)((E + 255) / 256), 256>>>(ei, E);
    scan1_kernel<<<nb, SCAN_B>>>(M);
    scan2_kernel<<<1, 1024>>>(nb);
    scan3_kernel<<<(M + 255) / 256, 256>>>(M);
    fill_kernel<<<(unsigned)((E + 255) / 256), 256>>>(ei, E);
    gemm1_mma<<<ntiles, 256, smem1>>>(x, M);
    gather1_kernel<<<(M * 32 + 255) / 256, 256>>>(M);
    gemm2_mma<<<ntiles, 256, smem2>>>(bc1, M);
    gather2_kernel<<<(M * 32 + 255) / 256, 256>>>(M);
    gemm3_mma<<<ntiles, 256, smem3>>>(bc2, M);
    decode_kernel<<<(unsigned)((EL * 32 + 255) / 256), 256>>>(eli, b1, W2, b2, out, EL);
}